// round 14
// baseline (speedup 1.0000x reference)
#include <cuda_runtime.h>
#include <cuda_bf16.h>
#include <cuda_fp16.h>
#include <cstdint>
#include <math.h>

#define Bsz 16
#define Lq 512
#define Lk 512
#define EMB 300
#define AH 256
#define ATT 250
#define ATT_IN 812
#define KA 832        // ATT_IN padded to 13*64
#define NP 768        // 3 heads * 256 (padded from 750)
#define RNN_IN 1280
#define Hh 128
#define G4 512

#define NEGF (-3.402823466e38f)
#define LDT 72        // 64 + 8 pad (bf16 elems) -> 144B row stride, conflict-free

// ==================== scratch (device globals) ====================
__device__ alignas(16) __nv_bfloat16 g_x1h[Bsz*Lq*KA], g_x1l[Bsz*Lq*KA];
__device__ alignas(16) __nv_bfloat16 g_x2h[Bsz*Lk*KA], g_x2l[Bsz*Lk*KA];
__device__ alignas(16) __nv_bfloat16 g_wh[NP*KA],      g_wl[NP*KA];
__device__ alignas(16) __nv_bfloat16 g_r1h[Bsz*Lq*NP], g_r1l[Bsz*Lq*NP];
__device__ alignas(16) __nv_bfloat16 g_r2h[Bsz*Lk*NP], g_r2l[Bsz*Lk*NP];
__device__ alignas(16) float         g_scores[48*Lq*Lk];
__device__ alignas(16) __half        g_ah[48*Lq*Lk];            // alpha, single fp16
__device__ alignas(16) __half        g_vth[3*Bsz*AH*Lk], g_vtl[3*Bsz*AH*Lk];  // V fp16 hi/lo
__device__ alignas(16) __nv_bfloat16 g_xch[Lq*Bsz*RNN_IN], g_xcl[Lq*Bsz*RNN_IN];
__device__ alignas(16) __nv_bfloat16 g_wfh[G4*RNN_IN], g_wfl[G4*RNN_IN];
__device__ alignas(16) __nv_bfloat16 g_wbh[G4*RNN_IN], g_wbl[G4*RNN_IN];
__device__ alignas(16) float g_gf[Lq*Bsz*G4];
__device__ alignas(16) float g_gb[Lq*Bsz*G4];
__device__ alignas(16) float g_vpad[NP];

__device__ __forceinline__ void bsplit(float v, __nv_bfloat16& h, __nv_bfloat16& l) {
    h = __float2bfloat16(v);
    l = __float2bfloat16(v - __bfloat162float(h));
}
__device__ __forceinline__ void hsplit(float v, __half& h, __half& l) {
    h = __float2half(v);
    l = __float2half(v - __half2float(h));
}

__device__ __forceinline__ uint32_t smem_u32(const void* p) {
    uint32_t a;
    asm("{ .reg .u64 t; cvta.to.shared.u64 t, %1; cvt.u32.u64 %0, t; }"
        : "=r"(a) : "l"(p));
    return a;
}

#define LDSM_X4(r, addr) \
    asm volatile("ldmatrix.sync.aligned.m8n8.x4.shared.b16 {%0,%1,%2,%3}, [%4];" \
        : "=r"((r)[0]), "=r"((r)[1]), "=r"((r)[2]), "=r"((r)[3]) : "r"(addr))

#define MMA16816(d, a, bb0, bb1) \
    asm volatile("mma.sync.aligned.m16n8k16.row.col.f32.bf16.bf16.f32 " \
        "{%0,%1,%2,%3}, {%4,%5,%6,%7}, {%8,%9}, {%0,%1,%2,%3};" \
        : "+f"((d)[0]), "+f"((d)[1]), "+f"((d)[2]), "+f"((d)[3]) \
        : "r"((a)[0]), "r"((a)[1]), "r"((a)[2]), "r"((a)[3]), "r"(bb0), "r"(bb1))

#define MMA16816H(d, a, bb0, bb1) \
    asm volatile("mma.sync.aligned.m16n8k16.row.col.f32.f16.f16.f32 " \
        "{%0,%1,%2,%3}, {%4,%5,%6,%7}, {%8,%9}, {%0,%1,%2,%3};" \
        : "+f"((d)[0]), "+f"((d)[1]), "+f"((d)[2]), "+f"((d)[3]) \
        : "r"((a)[0]), "r"((a)[1]), "r"((a)[2]), "r"((a)[3]), "r"(bb0), "r"(bb1))

#define CP16(dst, src) \
    asm volatile("cp.async.cg.shared.global [%0], [%1], 16;" :: "r"(dst), "l"(src))
#define CP_COMMIT() asm volatile("cp.async.commit_group;" ::: "memory")
#define CP_WAIT2()  asm volatile("cp.async.wait_group 2;" ::: "memory")
#define CP_WAIT1()  asm volatile("cp.async.wait_group 1;" ::: "memory")
#define CP_WAIT0()  asm volatile("cp.async.wait_group 0;" ::: "memory")

// packed f32x2 FMA (Blackwell)
#define FMA2(d, a, b) \
    asm("fma.rn.f32x2 %0, %1, %2, %3;" : "=l"(d) : "l"(a), "l"(b), "l"(d))

// ==================== builders ====================
__global__ void pad_w_kernel(const float* __restrict__ W)
{
    int idx = blockIdx.x * blockDim.x + threadIdx.x;
    if (idx >= NP * KA) return;
    int k = idx % KA, rr = idx / KA;
    int i = rr >> 8, j = rr & 255;
    float v = (j < ATT && k < ATT_IN) ? W[((size_t)(i * ATT + j)) * ATT_IN + k] : 0.f;
    bsplit(v, g_wh[idx], g_wl[idx]);
}

__global__ void vpad_kernel(const float* __restrict__ v)
{
    int n = blockIdx.x * blockDim.x + threadIdx.x;
    if (n >= NP) return;
    int i = n >> 8, j = n & 255;
    g_vpad[n] = (j < ATT) ? v[i * ATT + j] : 0.f;
}

__global__ void conv_split_kernel(const float* __restrict__ src,
                                  __nv_bfloat16* __restrict__ dh,
                                  __nv_bfloat16* __restrict__ dl, int n)
{
    int idx = blockIdx.x * blockDim.x + threadIdx.x;
    if (idx >= n) return;
    bsplit(src[idx], dh[idx], dl[idx]);
}

// merged x1/x2 builder: blockIdx.y selects side
__global__ void build_att_kernel(const float* __restrict__ w1,
                                 const float* __restrict__ a10,
                                 const float* __restrict__ a11,
                                 const float* __restrict__ w2,
                                 const float* __restrict__ a20,
                                 const float* __restrict__ a21)
{
    int idx = blockIdx.x * blockDim.x + threadIdx.x;
    if (idx >= Bsz * Lq * KA) return;
    int z = blockIdx.y;
    const float* w  = z ? w2  : w1;
    const float* a0 = z ? a20 : a10;
    const float* a1 = z ? a21 : a11;
    __nv_bfloat16* dh = z ? g_x2h : g_x1h;
    __nv_bfloat16* dl = z ? g_x2l : g_x1l;
    int f = idx % KA;
    int bl = idx / KA;
    float v = 0.f;
    if (f < EMB)            v = w[(size_t)bl * EMB + f];
    else if (f < EMB + AH)  v = a0[(size_t)bl * AH + (f - EMB)];
    else if (f < ATT_IN)    v = a1[(size_t)bl * AH + (f - EMB - AH)];
    bsplit(v, dh[idx], dl[idx]);
}

__global__ void fill_x1cat_base(const float* __restrict__ a0,
                                const float* __restrict__ a1)
{
    int idx = blockIdx.x * blockDim.x + threadIdx.x;
    if (idx >= Lq * Bsz * 2 * AH) return;
    int f = idx % (2 * AH);
    int lb = idx / (2 * AH);
    int l = lb / Bsz, b = lb % Bsz;
    float v = (f < AH) ? a0[((size_t)b * Lq + l) * AH + f]
                       : a1[((size_t)b * Lq + l) * AH + (f - AH)];
    size_t off = (size_t)lb * RNN_IN + f;
    bsplit(v, g_xch[off], g_xcl[off]);
}

// V transpose: fp16 hi/lo split
__global__ void vt_build_kernel(const float* __restrict__ a0,
                                const float* __restrict__ a1,
                                const float* __restrict__ a2)
{
    int idx = blockIdx.x * blockDim.x + threadIdx.x;
    if (idx >= 3 * Bsz * AH * Lk) return;
    int l = idx & 511, d = (idx >> 9) & 255, b = (idx >> 17) & 15, i = idx >> 21;
    const float* src = (i == 0) ? a0 : (i == 1 ? a1 : a2);
    hsplit(src[((size_t)b * Lk + l) * AH + d], g_vth[idx], g_vtl[idx]);
}

// ==================== warp-mma GEMM: R12 proven config + fp16 2-pass mode 3 ====================
// 256 threads, 8 warps of 64x32, CTA tile 128x128, k-chunk 64, 3-stage cp.async ring.
// mode 0: projections (bf16 3-pass).  z=0: r1 = relu(x1@W^T) split.  z=1: r2 *v split.
// mode 2: scores[z] = r1_i @ r2_i^T (48), bf16 3-pass
// mode 3: x1cat[...] = alpha[z] @ Vt (48), FP16 2-PASS (a_h x V_h + a_h x V_l), split out
// mode 4: gates (bf16 3-pass). z=0: gf = x1cat@Wf^T + bf.  z=1: gb (Wb, bb).
// epi: 0 fp32  1 relu->split  2 relu*vec->split  3 ->split  4 +vec->fp32
#define TGB (4 * 128 * LDT * 2)     // 73728 B per stage
#define TG_SMEM (3 * TGB)           // 221184 B

__global__ void __launch_bounds__(256)
tgemm_kernel(int mode, const float* __restrict__ v0, const float* __restrict__ v1)
{
    extern __shared__ char smem[];

    const __nv_bfloat16 *Ah, *Al, *Bh, *Bl;
    float* Cf = nullptr;
    __nv_bfloat16 *Coh = nullptr, *Col = nullptr;
    const float* vec = v0;
    int lda, ldb, ldc, K, epi;
    const bool f16p = (mode == 3);   // fp16 2-pass path

    if (mode == 0) {
        int z = blockIdx.z;
        Ah = z ? g_x2h : g_x1h; Al = z ? g_x2l : g_x1l;
        Bh = g_wh; Bl = g_wl;
        Coh = z ? g_r2h : g_r1h; Col = z ? g_r2l : g_r1l;
        lda = KA; ldb = KA; ldc = NP; K = KA;
        epi = z ? 2 : 1; vec = g_vpad;
    } else if (mode == 2) {
        int z = blockIdx.z, b = z / 3, i = z - b * 3;
        size_t off = (size_t)b * Lq * NP + (size_t)i * 256;
        Ah = g_r1h + off; Al = g_r1l + off;
        Bh = g_r2h + off; Bl = g_r2l + off;
        Cf = g_scores + (size_t)z * Lq * Lk;
        lda = NP; ldb = NP; ldc = Lk; K = 256; epi = 0;
    } else if (mode == 3) {
        int z = blockIdx.z, b = z / 3, i = z - b * 3;
        Ah = (const __nv_bfloat16*)(g_ah + (size_t)z * Lq * Lk); Al = Ah;
        size_t boff = (size_t)(i * Bsz + b) * AH * Lk;
        Bh = (const __nv_bfloat16*)(g_vth + boff);
        Bl = (const __nv_bfloat16*)(g_vtl + boff);
        size_t coff = (size_t)b * RNN_IN + 2 * AH + (size_t)i * AH;
        Coh = g_xch + coff; Col = g_xcl + coff;
        lda = Lk; ldb = Lk; ldc = Bsz * RNN_IN; K = Lk; epi = 3;
    } else {
        int z = blockIdx.z;
        Ah = g_xch; Al = g_xcl;
        Bh = z ? g_wbh : g_wfh; Bl = z ? g_wbl : g_wfl;
        Cf = z ? g_gb : g_gf;
        vec = z ? v1 : v0;
        lda = RNN_IN; ldb = RNN_IN; ldc = G4; K = RNN_IN; epi = 4;
    }

    int m0 = blockIdx.y * 128, n0 = blockIdx.x * 128;
    int tid = threadIdx.x, lane = tid & 31, wid = tid >> 5;
    int wm = (wid >> 2) * 64, wn = (wid & 3) * 32;

    float acc[4][4][4];
    #pragma unroll
    for (int a = 0; a < 4; a++)
        #pragma unroll
        for (int b = 0; b < 4; b++)
            #pragma unroll
            for (int c = 0; c < 4; c++) acc[a][b][c] = 0.f;

    int arow = lane & 15, akk = (lane >> 4) * 8;
    int brow = (lane & 7) + ((lane >> 4) * 8), bkk = ((lane >> 3) & 1) * 8;

    uint32_t sbase = smem_u32(smem);
    const uint32_t tB = 128 * LDT * 2;      // one tile, bytes

    int ldrow = tid >> 3, ldc8 = (tid & 7) * 8;
    uint32_t so0 = (uint32_t)((ldrow * LDT + ldc8) * 2);

    int nch = K >> 6;

    auto issue = [&](int kc, int buf) {
        int kb = kc * 64;
        uint32_t bb = sbase + buf * TGB;
        #pragma unroll
        for (int i = 0; i < 4; i++) {
            int row = ldrow + i * 32;
            uint32_t so = bb + so0 + (uint32_t)(i * 32 * LDT * 2);
            CP16(so,          Ah + (size_t)(m0 + row) * lda + kb + ldc8);
            CP16(so + 2 * tB, Bh + (size_t)(n0 + row) * ldb + kb + ldc8);
            CP16(so + 3 * tB, Bl + (size_t)(n0 + row) * ldb + kb + ldc8);
            if (!f16p)
                CP16(so + tB, Al + (size_t)(m0 + row) * lda + kb + ldc8);
        }
        CP_COMMIT();
    };

    issue(0, 0);
    if (nch > 1) issue(1, 1);

    for (int kc = 0; kc < nch; kc++) {
        int buf = kc % 3;
        if (kc + 2 < nch)      { issue(kc + 2, (kc + 2) % 3); CP_WAIT2(); }
        else if (kc + 1 < nch) { CP_WAIT1(); }
        else                   { CP_WAIT0(); }
        __syncthreads();

        uint32_t bb = sbase + buf * TGB;
        uint32_t adAh = bb + ((wm + arow) * LDT + akk) * 2;
        uint32_t adAl = adAh + tB;
        uint32_t adBh = bb + 2 * tB + ((wn + brow) * LDT + bkk) * 2;
        uint32_t adBl = adBh + tB;

        // hi fragments double-buffered across ks
        uint32_t fah[2][4][4], fbh[2][2][4];
        #pragma unroll
        for (int mt = 0; mt < 4; mt++) LDSM_X4(fah[0][mt], adAh + mt * 16 * LDT * 2);
        #pragma unroll
        for (int p = 0; p < 2; p++)    LDSM_X4(fbh[0][p], adBh + p * 16 * LDT * 2);

        #pragma unroll
        for (int ks = 0; ks < 4; ks++) {
            const int cur = ks & 1, nxt = cur ^ 1;
            int ko = ks * 32;

            uint32_t fbl[2][4], fal[4][4];
            #pragma unroll
            for (int p = 0; p < 2; p++)    LDSM_X4(fbl[p], adBl + p * 16 * LDT * 2 + ko);
            if (!f16p) {
                #pragma unroll
                for (int mt = 0; mt < 4; mt++) LDSM_X4(fal[mt], adAl + mt * 16 * LDT * 2 + ko);
            }
            if (ks < 3) {
                #pragma unroll
                for (int mt = 0; mt < 4; mt++) LDSM_X4(fah[nxt][mt], adAh + mt * 16 * LDT * 2 + ko + 32);
                #pragma unroll
                for (int p = 0; p < 2; p++)    LDSM_X4(fbh[nxt][p], adBh + p * 16 * LDT * 2 + ko + 32);
            }

            if (f16p) {
                // fp16 2-pass: a_h x V_h + a_h x V_l
                #pragma unroll
                for (int mt = 0; mt < 4; mt++)
                    #pragma unroll
                    for (int nt = 0; nt < 4; nt++)
                        MMA16816H(acc[mt][nt], fah[cur][mt],
                                  fbh[cur][nt >> 1][(nt & 1) * 2], fbh[cur][nt >> 1][(nt & 1) * 2 + 1]);
                #pragma unroll
                for (int mt = 0; mt < 4; mt++)
                    #pragma unroll
                    for (int nt = 0; nt < 4; nt++)
                        MMA16816H(acc[mt][nt], fah[cur][mt],
                                  fbl[nt >> 1][(nt & 1) * 2], fbl[nt >> 1][(nt & 1) * 2 + 1]);
            } else {
                // bf16 3-pass
                #pragma unroll
                for (int mt = 0; mt < 4; mt++)
                    #pragma unroll
                    for (int nt = 0; nt < 4; nt++)
                        MMA16816(acc[mt][nt], fah[cur][mt],
                                 fbh[cur][nt >> 1][(nt & 1) * 2], fbh[cur][nt >> 1][(nt & 1) * 2 + 1]);
                #pragma unroll
                for (int mt = 0; mt < 4; mt++)
                    #pragma unroll
                    for (int nt = 0; nt < 4; nt++)
                        MMA16816(acc[mt][nt], fah[cur][mt],
                                 fbl[nt >> 1][(nt & 1) * 2], fbl[nt >> 1][(nt & 1) * 2 + 1]);
                #pragma unroll
                for (int mt = 0; mt < 4; mt++)
                    #pragma unroll
                    for (int nt = 0; nt < 4; nt++)
                        MMA16816(acc[mt][nt], fal[mt],
                                 fbh[cur][nt >> 1][(nt & 1) * 2], fbh[cur][nt >> 1][(nt & 1) * 2 + 1]);
            }
        }
        __syncthreads();
    }

    // epilogue
    int er = lane >> 2, ec = (lane & 3) * 2;
    #pragma unroll
    for (int mt = 0; mt < 4; mt++) {
        #pragma unroll
        for (int nt = 0; nt < 4; nt++) {
            float* d = acc[mt][nt];
            int mr = m0 + wm + mt * 16 + er;
            int nc = n0 + wn + nt * 8 + ec;
            #pragma unroll
            for (int q = 0; q < 4; q++) {
                int m = mr + (q >> 1) * 8;
                int n = nc + (q & 1);
                float v = d[q];
                if (epi == 0) {
                    Cf[(size_t)m * ldc + n] = v;
                } else if (epi == 4) {
                    Cf[(size_t)m * ldc + n] = v + vec[n];
                } else {
                    if (epi == 1) v = fmaxf(v, 0.f);
                    else if (epi == 2) v = fmaxf(v, 0.f) * vec[n];
                    size_t o = (size_t)m * ldc + n;
                    __nv_bfloat16 h, l;
                    bsplit(v, h, l);
                    Coh[o] = h; Col[o] = l;
                }
            }
        }
    }
}

// ==================== masked softmax -> fp16 alpha ====================
__global__ void softmax_kernel(const unsigned char* __restrict__ mask)
{
    int gw = (blockIdx.x * blockDim.x + threadIdx.x) >> 5;
    int lane = threadIdx.x & 31;
    int z = gw >> 9;
    int b = z / 3;
    const float* s = g_scores + (size_t)gw * Lk;
    const unsigned char* mk = mask + b * Lk;

    float v[16];
    float mx = -INFINITY;
    #pragma unroll
    for (int t = 0; t < 16; t++) {
        int m = lane + t * 32;
        float x = s[m];
        if (mk[m]) x = NEGF;
        v[t] = x;
        mx = fmaxf(mx, x);
    }
    #pragma unroll
    for (int o = 16; o > 0; o >>= 1) mx = fmaxf(mx, __shfl_xor_sync(0xffffffffu, mx, o));
    float sum = 0.f;
    #pragma unroll
    for (int t = 0; t < 16; t++) { v[t] = expf(v[t] - mx); sum += v[t]; }
    #pragma unroll
    for (int o = 16; o > 0; o >>= 1) sum += __shfl_xor_sync(0xffffffffu, sum, o);
    float inv = 1.f / sum;
    size_t base = (size_t)gw * Lk;
    #pragma unroll
    for (int t = 0; t < 16; t++)
        g_ah[base + lane + t * 32] = __float2half(v[t] * inv);
}

// ==================== BiLSTM recurrence (88/40 weight split, R12 proven) ====================
#define LSTM_SMEM (512 * 16 * 16 + 128 * 4 + 512 * 4)

__global__ void __launch_bounds__(512, 1)
lstm_kernel(const float* __restrict__ WhhF, const float* __restrict__ WhhB,
            float* __restrict__ out)
{
    extern __shared__ float sm[];
    double2* Wsm2 = (double2*)sm;          // [512][16] double2 slots, swizzled, 10 used
    float*   hs   = sm + 32768;
    float*   as   = sm + 32768 + 128;

    int dir = blockIdx.x >> 4;
    int b   = blockIdx.x & 15;
    const float* Whh = dir ? WhhB : WhhF;
    const float* g   = dir ? g_gb : g_gf;
    int j = threadIdx.x;
    int grp = j >> 7;

    unsigned long long w2[44];
    #pragma unroll
    for (int c = 0; c < 22; c++) {
        double2 t = *(const double2*)(Whh + (size_t)j * Hh + c * 4);
        w2[2*c]   = __double_as_longlong(t.x);
        w2[2*c+1] = __double_as_longlong(t.y);
    }
    #pragma unroll
    for (int c = 0; c < 10; c++) {
        double2 t = *(const double2*)(Whh + (size_t)j * Hh + 88 + c * 4);
        Wsm2[j * 16 + (c ^ (j & 7))] = t;
    }
    if (j < Hh) hs[j] = 0.f;
    float cst = 0.f;
    __syncthreads();

    int l  = dir ? (Lq - 1) : 0;
    int dl = dir ? -1 : 1;
    float gval = g[((size_t)l * Bsz + b) * G4 + j];

    #pragma unroll 1
    for (int s = 0; s < Lq; s++) {
        float gnext = 0.f;
        if (s < Lq - 1) gnext = g[((size_t)(l + dl) * Bsz + b) * G4 + j];

        const double2* h2 = (const double2*)hs;
        unsigned long long p0 = (unsigned long long)__float_as_uint(gval);
        unsigned long long p1 = 0ull, p2 = 0ull, p3 = 0ull;
        #pragma unroll
        for (int c = 0; c < 22; c++) {
            double2 hv = h2[c];
            FMA2(p0, w2[2*c],   __double_as_longlong(hv.x));
            FMA2(p1, w2[2*c+1], __double_as_longlong(hv.y));
        }
        #pragma unroll
        for (int c = 0; c < 10; c++) {
            double2 hv = h2[22 + c];
            double2 wv = Wsm2[j * 16 + (c ^ (j & 7))];
            FMA2(p2, __double_as_longlong(wv.x), __double_as_longlong(hv.x));
            FMA2(p3, __double_as_longlong(wv.y), __double_as_longlong(hv.y));
        }
        float z = (__uint_as_float((unsigned)p0) + __uint_as_float((unsigned)(p0 >> 32)))
                + (__uint_as_float((unsigned)p1) + __uint_as_float((unsigned)(p1 >> 32)))
                + (__uint_as_float((unsigned)p2) + __uint_as_float((unsigned)(p2 >> 32)))
                + (__uint_as_float((unsigned)p3) + __uint_as_float((unsigned)(p3 >> 32)));
        as[j] = (grp == 2) ? tanhf(z) : (1.f / (1.f + expf(-z)));
        __syncthreads();

        if (j < Hh) {
            float si = as[j], sf = as[Hh + j], tg = as[2*Hh + j], so = as[3*Hh + j];
            cst = sf * cst + si * tg;
            float hv = so * tanhf(cst);
            hs[j] = hv;
            out[((size_t)b * Lq + l) * 256 + dir * Hh + j] = hv;
        }
        __syncthreads();
        gval = gnext;
        l += dl;
    }
}

// ==================== launcher ====================
extern "C" void kernel_launch(void* const* d_in, const int* in_sizes, int n_in,
                              void* d_out, int out_size)
{
    const float* x1_word = (const float*)d_in[0];
    const float* x1_a0   = (const float*)d_in[1];
    const float* x1_a1   = (const float*)d_in[2];
    const float* x2_word = (const float*)d_in[3];
    const float* x2_a0   = (const float*)d_in[4];
    const float* x2_a1   = (const float*)d_in[5];
    const float* x2_a2   = (const float*)d_in[6];
    const unsigned char* x2_mask = (const unsigned char*)d_in[8];
    const float* W_attn  = (const float*)d_in[9];
    const float* v_attn  = (const float*)d_in[10];
    const float* Wih_f   = (const float*)d_in[11];
    const float* Whh_f   = (const float*)d_in[12];
    const float* b_f     = (const float*)d_in[13];
    const float* Wih_b   = (const float*)d_in[14];
    const float* Whh_b   = (const float*)d_in[15];
    const float* b_b     = (const float*)d_in[16];
    float* out = (float*)d_out;

    cudaFuncSetAttribute(lstm_kernel,
                         cudaFuncAttributeMaxDynamicSharedMemorySize, LSTM_SMEM);
    cudaFuncSetAttribute(tgemm_kernel,
                         cudaFuncAttributeMaxDynamicSharedMemorySize, TG_SMEM);

    __nv_bfloat16 *p_wfh, *p_wfl, *p_wbh, *p_wbl;
    cudaGetSymbolAddress((void**)&p_wfh, g_wfh); cudaGetSymbolAddress((void**)&p_wfl, g_wfl);
    cudaGetSymbolAddress((void**)&p_wbh, g_wbh); cudaGetSymbolAddress((void**)&p_wbl, g_wbl);

    // launches 1-3: prerequisites of the projection GEMM
    vpad_kernel<<<3, 256>>>(v_attn);
    pad_w_kernel<<<(NP * KA + 255) / 256, 256>>>(W_attn);
    dim3 gb((Bsz * Lq * KA + 255) / 256, 2);
    build_att_kernel<<<gb, 256>>>(x1_word, x1_a0, x1_a1, x2_word, x2_a0, x2_a1);

    // launch 4 (profiled): merged projections M=8192 N=768 K=832, z in {x1,x2}
    dim3 gp(NP / 128, (Bsz * Lq) / 128, 2);
    tgemm_kernel<<<gp, 256, TG_SMEM>>>(0, nullptr, nullptr);

    conv_split_kernel<<<(G4 * RNN_IN + 255) / 256, 256>>>(Wih_f, p_wfh, p_wfl, G4 * RNN_IN);
    conv_split_kernel<<<(G4 * RNN_IN + 255) / 256, 256>>>(Wih_b, p_wbh, p_wbl, G4 * RNN_IN);
    fill_x1cat_base<<<(Lq * Bsz * 2 * AH + 255) / 256, 256>>>(x1_a0, x1_a1);
    vt_build_kernel<<<(3 * Bsz * AH * Lk + 255) / 256, 256>>>(x2_a0, x2_a1, x2_a2);

    // scores : 48 x [512,512,K=256], bf16 3-pass
    dim3 gs(Lk / 128, Lq / 128, 48);
    tgemm_kernel<<<gs, 256, TG_SMEM>>>(2, nullptr, nullptr);

    softmax_kernel<<<(48 * Lq) / 8, 256>>>(x2_mask);

    // alpha @ V : 48 x [512,256,K=512], fp16 2-pass
    dim3 gav(AH / 128, Lq / 128, 48);
    tgemm_kernel<<<gav, 256, TG_SMEM>>>(3, nullptr, nullptr);

    // LSTM input gates merged: M=8192, N=512, K=1280, z in {f,b}, bf16 3-pass
    dim3 gg(G4 / 128, (Bsz * Lq) / 128, 2);
    tgemm_kernel<<<gg, 256, TG_SMEM>>>(4, b_f, b_b);

    lstm_kernel<<<32, 512, LSTM_SMEM>>>(Whh_f, Whh_b, out);
}

// round 15
// speedup vs baseline: 1.0411x; 1.0411x over previous
#include <cuda_runtime.h>
#include <cuda_bf16.h>
#include <cuda_fp16.h>
#include <cstdint>
#include <math.h>

#define Bsz 16
#define Lq 512
#define Lk 512
#define EMB 300
#define AH 256
#define ATT 250
#define ATT_IN 812
#define KA 832        // ATT_IN padded to 13*64
#define NP 768        // 3 heads * 256 (padded from 750)
#define RNN_IN 1280
#define Hh 128
#define G4 512

#define NEGF (-3.402823466e38f)
#define LDT 72        // 64 + 8 pad (bf16 elems) -> 144B row stride, conflict-free

// ==================== scratch (device globals) ====================
__device__ alignas(16) __nv_bfloat16 g_x1h[Bsz*Lq*KA], g_x1l[Bsz*Lq*KA];
__device__ alignas(16) __nv_bfloat16 g_x2h[Bsz*Lk*KA], g_x2l[Bsz*Lk*KA];
__device__ alignas(16) __nv_bfloat16 g_wh[NP*KA],      g_wl[NP*KA];
__device__ alignas(16) __nv_bfloat16 g_r1h[Bsz*Lq*NP], g_r1l[Bsz*Lq*NP];
__device__ alignas(16) __nv_bfloat16 g_r2h[Bsz*Lk*NP], g_r2l[Bsz*Lk*NP];
__device__ alignas(16) float         g_scores[48*Lq*Lk];
__device__ alignas(16) __half        g_ah[48*Lq*Lk];            // alpha, single fp16
__device__ alignas(16) __half        g_vth[3*Bsz*AH*Lk], g_vtl[3*Bsz*AH*Lk];  // V fp16 hi/lo
__device__ alignas(16) __nv_bfloat16 g_xch[Lq*Bsz*RNN_IN], g_xcl[Lq*Bsz*RNN_IN];
__device__ alignas(16) __nv_bfloat16 g_wfh[G4*RNN_IN], g_wfl[G4*RNN_IN];
__device__ alignas(16) __nv_bfloat16 g_wbh[G4*RNN_IN], g_wbl[G4*RNN_IN];
__device__ alignas(16) float g_gf[Lq*Bsz*G4];
__device__ alignas(16) float g_gb[Lq*Bsz*G4];
__device__ alignas(16) float g_vpad[NP];

__device__ __forceinline__ void bsplit(float v, __nv_bfloat16& h, __nv_bfloat16& l) {
    h = __float2bfloat16(v);
    l = __float2bfloat16(v - __bfloat162float(h));
}
__device__ __forceinline__ void hsplit(float v, __half& h, __half& l) {
    h = __float2half(v);
    l = __float2half(v - __half2float(h));
}

__device__ __forceinline__ uint32_t smem_u32(const void* p) {
    uint32_t a;
    asm("{ .reg .u64 t; cvta.to.shared.u64 t, %1; cvt.u32.u64 %0, t; }"
        : "=r"(a) : "l"(p));
    return a;
}

#define LDSM_X4(r, addr) \
    asm volatile("ldmatrix.sync.aligned.m8n8.x4.shared.b16 {%0,%1,%2,%3}, [%4];" \
        : "=r"((r)[0]), "=r"((r)[1]), "=r"((r)[2]), "=r"((r)[3]) : "r"(addr))

#define MMA16816(d, a, bb0, bb1) \
    asm volatile("mma.sync.aligned.m16n8k16.row.col.f32.bf16.bf16.f32 " \
        "{%0,%1,%2,%3}, {%4,%5,%6,%7}, {%8,%9}, {%0,%1,%2,%3};" \
        : "+f"((d)[0]), "+f"((d)[1]), "+f"((d)[2]), "+f"((d)[3]) \
        : "r"((a)[0]), "r"((a)[1]), "r"((a)[2]), "r"((a)[3]), "r"(bb0), "r"(bb1))

#define MMA16816H(d, a, bb0, bb1) \
    asm volatile("mma.sync.aligned.m16n8k16.row.col.f32.f16.f16.f32 " \
        "{%0,%1,%2,%3}, {%4,%5,%6,%7}, {%8,%9}, {%0,%1,%2,%3};" \
        : "+f"((d)[0]), "+f"((d)[1]), "+f"((d)[2]), "+f"((d)[3]) \
        : "r"((a)[0]), "r"((a)[1]), "r"((a)[2]), "r"((a)[3]), "r"(bb0), "r"(bb1))

#define CP16(dst, src) \
    asm volatile("cp.async.cg.shared.global [%0], [%1], 16;" :: "r"(dst), "l"(src))
#define CP_COMMIT() asm volatile("cp.async.commit_group;" ::: "memory")
#define CP_WAIT2()  asm volatile("cp.async.wait_group 2;" ::: "memory")
#define CP_WAIT1()  asm volatile("cp.async.wait_group 1;" ::: "memory")
#define CP_WAIT0()  asm volatile("cp.async.wait_group 0;" ::: "memory")

// packed f32x2 FMA (Blackwell)
#define FMA2(d, a, b) \
    asm("fma.rn.f32x2 %0, %1, %2, %3;" : "=l"(d) : "l"(a), "l"(b), "l"(d))

// ==================== builders ====================
__global__ void pad_w_kernel(const float* __restrict__ W)
{
    int idx = blockIdx.x * blockDim.x + threadIdx.x;
    if (idx >= NP * KA) return;
    int k = idx % KA, rr = idx / KA;
    int i = rr >> 8, j = rr & 255;
    float v = (j < ATT && k < ATT_IN) ? W[((size_t)(i * ATT + j)) * ATT_IN + k] : 0.f;
    bsplit(v, g_wh[idx], g_wl[idx]);
}

__global__ void vpad_kernel(const float* __restrict__ v)
{
    int n = blockIdx.x * blockDim.x + threadIdx.x;
    if (n >= NP) return;
    int i = n >> 8, j = n & 255;
    g_vpad[n] = (j < ATT) ? v[i * ATT + j] : 0.f;
}

__global__ void conv_split_kernel(const float* __restrict__ src,
                                  __nv_bfloat16* __restrict__ dh,
                                  __nv_bfloat16* __restrict__ dl, int n)
{
    int idx = blockIdx.x * blockDim.x + threadIdx.x;
    if (idx >= n) return;
    bsplit(src[idx], dh[idx], dl[idx]);
}

// merged x1/x2 builder: blockIdx.y selects side
__global__ void build_att_kernel(const float* __restrict__ w1,
                                 const float* __restrict__ a10,
                                 const float* __restrict__ a11,
                                 const float* __restrict__ w2,
                                 const float* __restrict__ a20,
                                 const float* __restrict__ a21)
{
    int idx = blockIdx.x * blockDim.x + threadIdx.x;
    if (idx >= Bsz * Lq * KA) return;
    int z = blockIdx.y;
    const float* w  = z ? w2  : w1;
    const float* a0 = z ? a20 : a10;
    const float* a1 = z ? a21 : a11;
    __nv_bfloat16* dh = z ? g_x2h : g_x1h;
    __nv_bfloat16* dl = z ? g_x2l : g_x1l;
    int f = idx % KA;
    int bl = idx / KA;
    float v = 0.f;
    if (f < EMB)            v = w[(size_t)bl * EMB + f];
    else if (f < EMB + AH)  v = a0[(size_t)bl * AH + (f - EMB)];
    else if (f < ATT_IN)    v = a1[(size_t)bl * AH + (f - EMB - AH)];
    bsplit(v, dh[idx], dl[idx]);
}

__global__ void fill_x1cat_base(const float* __restrict__ a0,
                                const float* __restrict__ a1)
{
    int idx = blockIdx.x * blockDim.x + threadIdx.x;
    if (idx >= Lq * Bsz * 2 * AH) return;
    int f = idx % (2 * AH);
    int lb = idx / (2 * AH);
    int l = lb / Bsz, b = lb % Bsz;
    float v = (f < AH) ? a0[((size_t)b * Lq + l) * AH + f]
                       : a1[((size_t)b * Lq + l) * AH + (f - AH)];
    size_t off = (size_t)lb * RNN_IN + f;
    bsplit(v, g_xch[off], g_xcl[off]);
}

// V transpose: fp16 hi/lo split
__global__ void vt_build_kernel(const float* __restrict__ a0,
                                const float* __restrict__ a1,
                                const float* __restrict__ a2)
{
    int idx = blockIdx.x * blockDim.x + threadIdx.x;
    if (idx >= 3 * Bsz * AH * Lk) return;
    int l = idx & 511, d = (idx >> 9) & 255, b = (idx >> 17) & 15, i = idx >> 21;
    const float* src = (i == 0) ? a0 : (i == 1 ? a1 : a2);
    hsplit(src[((size_t)b * Lk + l) * AH + d], g_vth[idx], g_vtl[idx]);
}

// ==================== bf16 3-pass GEMM: exact R12 body (modes 0/2/4) ====================
// 256 threads, 8 warps of 64x32, CTA tile 128x128, k-chunk 64, 3-stage cp.async ring.
// mode 0: projections.  z=0: r1 = relu(x1@W^T) split.  z=1: r2 = relu(x2@W^T)*v split.
// mode 2: scores[z] = r1_i @ r2_i^T (48)
// mode 4: gates. z=0: gf = x1cat@Wf^T + bf.  z=1: gb (Wb, bb).
// epi: 0 fp32  1 relu->split  2 relu*vec->split  4 +vec->fp32
#define TGB (4 * 128 * LDT * 2)     // 73728 B per stage
#define TG_SMEM (3 * TGB)           // 221184 B

__global__ void __launch_bounds__(256)
tgemm_kernel(int mode, const float* __restrict__ v0, const float* __restrict__ v1)
{
    extern __shared__ char smem[];

    const __nv_bfloat16 *Ah, *Al, *Bh, *Bl;
    float* Cf = nullptr;
    __nv_bfloat16 *Coh = nullptr, *Col = nullptr;
    const float* vec = v0;
    int lda, ldb, ldc, K, epi;

    if (mode == 0) {
        int z = blockIdx.z;
        Ah = z ? g_x2h : g_x1h; Al = z ? g_x2l : g_x1l;
        Bh = g_wh; Bl = g_wl;
        Coh = z ? g_r2h : g_r1h; Col = z ? g_r2l : g_r1l;
        lda = KA; ldb = KA; ldc = NP; K = KA;
        epi = z ? 2 : 1; vec = g_vpad;
    } else if (mode == 2) {
        int z = blockIdx.z, b = z / 3, i = z - b * 3;
        size_t off = (size_t)b * Lq * NP + (size_t)i * 256;
        Ah = g_r1h + off; Al = g_r1l + off;
        Bh = g_r2h + off; Bl = g_r2l + off;
        Cf = g_scores + (size_t)z * Lq * Lk;
        lda = NP; ldb = NP; ldc = Lk; K = 256; epi = 0;
    } else {
        int z = blockIdx.z;
        Ah = g_xch; Al = g_xcl;
        Bh = z ? g_wbh : g_wfh; Bl = z ? g_wbl : g_wfl;
        Cf = z ? g_gb : g_gf;
        vec = z ? v1 : v0;
        lda = RNN_IN; ldb = RNN_IN; ldc = G4; K = RNN_IN; epi = 4;
    }

    int m0 = blockIdx.y * 128, n0 = blockIdx.x * 128;
    int tid = threadIdx.x, lane = tid & 31, wid = tid >> 5;
    int wm = (wid >> 2) * 64, wn = (wid & 3) * 32;

    float acc[4][4][4];
    #pragma unroll
    for (int a = 0; a < 4; a++)
        #pragma unroll
        for (int b = 0; b < 4; b++)
            #pragma unroll
            for (int c = 0; c < 4; c++) acc[a][b][c] = 0.f;

    int arow = lane & 15, akk = (lane >> 4) * 8;
    int brow = (lane & 7) + ((lane >> 4) * 8), bkk = ((lane >> 3) & 1) * 8;

    uint32_t sbase = smem_u32(smem);
    const uint32_t tB = 128 * LDT * 2;      // one tile, bytes

    int ldrow = tid >> 3, ldc8 = (tid & 7) * 8;
    uint32_t so0 = (uint32_t)((ldrow * LDT + ldc8) * 2);

    int nch = K >> 6;

    auto issue = [&](int kc, int buf) {
        int kb = kc * 64;
        uint32_t bb = sbase + buf * TGB;
        #pragma unroll
        for (int i = 0; i < 4; i++) {
            int row = ldrow + i * 32;
            uint32_t so = bb + so0 + (uint32_t)(i * 32 * LDT * 2);
            CP16(so,          Ah + (size_t)(m0 + row) * lda + kb + ldc8);
            CP16(so + tB,     Al + (size_t)(m0 + row) * lda + kb + ldc8);
            CP16(so + 2 * tB, Bh + (size_t)(n0 + row) * ldb + kb + ldc8);
            CP16(so + 3 * tB, Bl + (size_t)(n0 + row) * ldb + kb + ldc8);
        }
        CP_COMMIT();
    };

    issue(0, 0);
    if (nch > 1) issue(1, 1);

    for (int kc = 0; kc < nch; kc++) {
        int buf = kc % 3;
        if (kc + 2 < nch)      { issue(kc + 2, (kc + 2) % 3); CP_WAIT2(); }
        else if (kc + 1 < nch) { CP_WAIT1(); }
        else                   { CP_WAIT0(); }
        __syncthreads();

        uint32_t bb = sbase + buf * TGB;
        uint32_t adAh = bb + ((wm + arow) * LDT + akk) * 2;
        uint32_t adAl = adAh + tB;
        uint32_t adBh = bb + 2 * tB + ((wn + brow) * LDT + bkk) * 2;
        uint32_t adBl = adBh + tB;

        // hi fragments double-buffered across ks
        uint32_t fah[2][4][4], fbh[2][2][4];
        #pragma unroll
        for (int mt = 0; mt < 4; mt++) LDSM_X4(fah[0][mt], adAh + mt * 16 * LDT * 2);
        #pragma unroll
        for (int p = 0; p < 2; p++)    LDSM_X4(fbh[0][p], adBh + p * 16 * LDT * 2);

        #pragma unroll
        for (int ks = 0; ks < 4; ks++) {
            const int cur = ks & 1, nxt = cur ^ 1;
            int ko = ks * 32;

            uint32_t fbl[2][4], fal[4][4];
            #pragma unroll
            for (int p = 0; p < 2; p++)    LDSM_X4(fbl[p], adBl + p * 16 * LDT * 2 + ko);
            #pragma unroll
            for (int mt = 0; mt < 4; mt++) LDSM_X4(fal[mt], adAl + mt * 16 * LDT * 2 + ko);
            if (ks < 3) {
                #pragma unroll
                for (int mt = 0; mt < 4; mt++) LDSM_X4(fah[nxt][mt], adAh + mt * 16 * LDT * 2 + ko + 32);
                #pragma unroll
                for (int p = 0; p < 2; p++)    LDSM_X4(fbh[nxt][p], adBh + p * 16 * LDT * 2 + ko + 32);
            }

            #pragma unroll
            for (int mt = 0; mt < 4; mt++)
                #pragma unroll
                for (int nt = 0; nt < 4; nt++)
                    MMA16816(acc[mt][nt], fah[cur][mt],
                             fbh[cur][nt >> 1][(nt & 1) * 2], fbh[cur][nt >> 1][(nt & 1) * 2 + 1]);
            #pragma unroll
            for (int mt = 0; mt < 4; mt++)
                #pragma unroll
                for (int nt = 0; nt < 4; nt++)
                    MMA16816(acc[mt][nt], fah[cur][mt],
                             fbl[nt >> 1][(nt & 1) * 2], fbl[nt >> 1][(nt & 1) * 2 + 1]);
            #pragma unroll
            for (int mt = 0; mt < 4; mt++)
                #pragma unroll
                for (int nt = 0; nt < 4; nt++)
                    MMA16816(acc[mt][nt], fal[mt],
                             fbh[cur][nt >> 1][(nt & 1) * 2], fbh[cur][nt >> 1][(nt & 1) * 2 + 1]);
        }
        __syncthreads();
    }

    // epilogue
    int er = lane >> 2, ec = (lane & 3) * 2;
    #pragma unroll
    for (int mt = 0; mt < 4; mt++) {
        #pragma unroll
        for (int nt = 0; nt < 4; nt++) {
            float* d = acc[mt][nt];
            int mr = m0 + wm + mt * 16 + er;
            int nc = n0 + wn + nt * 8 + ec;
            #pragma unroll
            for (int q = 0; q < 4; q++) {
                int m = mr + (q >> 1) * 8;
                int n = nc + (q & 1);
                float v = d[q];
                if (epi == 0) {
                    Cf[(size_t)m * ldc + n] = v;
                } else if (epi == 4) {
                    Cf[(size_t)m * ldc + n] = v + vec[n];
                } else {
                    if (epi == 1) v = fmaxf(v, 0.f);
                    else if (epi == 2) v = fmaxf(v, 0.f) * vec[n];
                    size_t o = (size_t)m * ldc + n;
                    __nv_bfloat16 h, l;
                    bsplit(v, h, l);
                    Coh[o] = h; Col[o] = l;
                }
            }
        }
    }
}

// ==================== fp16 2-pass alpha@V GEMM (dedicated kernel) ====================
// x1cat[b][l][512 + i*256 + n] = sum_m alpha[z][l][m] * Vt[i,b][n][m]
// A = alpha (fp16, single), B = V hi + lo (fp16). 2 passes. Split bf16 output.
__global__ void __launch_bounds__(256)
tgemm_av_kernel()
{
    extern __shared__ char smem[];

    int z = blockIdx.z, b = z / 3, i = z - b * 3;
    const __half* Ax = g_ah + (size_t)z * Lq * Lk;
    size_t boff = (size_t)(i * Bsz + b) * AH * Lk;
    const __half* Bh = g_vth + boff;
    const __half* Bl = g_vtl + boff;
    size_t coff = (size_t)b * RNN_IN + 2 * AH + (size_t)i * AH;
    __nv_bfloat16* Coh = g_xch + coff;
    __nv_bfloat16* Col = g_xcl + coff;
    const int lda = Lk, ldb = Lk, ldc = Bsz * RNN_IN, K = Lk;

    int m0 = blockIdx.y * 128, n0 = blockIdx.x * 128;
    int tid = threadIdx.x, lane = tid & 31, wid = tid >> 5;
    int wm = (wid >> 2) * 64, wn = (wid & 3) * 32;

    float acc[4][4][4];
    #pragma unroll
    for (int a = 0; a < 4; a++)
        #pragma unroll
        for (int bq = 0; bq < 4; bq++)
            #pragma unroll
            for (int c = 0; c < 4; c++) acc[a][bq][c] = 0.f;

    int arow = lane & 15, akk = (lane >> 4) * 8;
    int brow = (lane & 7) + ((lane >> 4) * 8), bkk = ((lane >> 3) & 1) * 8;

    uint32_t sbase = smem_u32(smem);
    const uint32_t tB = 128 * LDT * 2;

    int ldrow = tid >> 3, ldc8 = (tid & 7) * 8;
    uint32_t so0 = (uint32_t)((ldrow * LDT + ldc8) * 2);

    int nch = K >> 6;

    auto issue = [&](int kc, int buf) {
        int kb = kc * 64;
        uint32_t bb = sbase + buf * TGB;
        #pragma unroll
        for (int u = 0; u < 4; u++) {
            int row = ldrow + u * 32;
            uint32_t so = bb + so0 + (uint32_t)(u * 32 * LDT * 2);
            CP16(so,          Ax + (size_t)(m0 + row) * lda + kb + ldc8);
            CP16(so + tB,     Bh + (size_t)(n0 + row) * ldb + kb + ldc8);
            CP16(so + 2 * tB, Bl + (size_t)(n0 + row) * ldb + kb + ldc8);
        }
        CP_COMMIT();
    };

    issue(0, 0);
    if (nch > 1) issue(1, 1);

    for (int kc = 0; kc < nch; kc++) {
        int buf = kc % 3;
        if (kc + 2 < nch)      { issue(kc + 2, (kc + 2) % 3); CP_WAIT2(); }
        else if (kc + 1 < nch) { CP_WAIT1(); }
        else                   { CP_WAIT0(); }
        __syncthreads();

        uint32_t bb = sbase + buf * TGB;
        uint32_t adA  = bb + ((wm + arow) * LDT + akk) * 2;
        uint32_t adBh = bb + tB + ((wn + brow) * LDT + bkk) * 2;
        uint32_t adBl = adBh + tB;

        #pragma unroll
        for (int ks = 0; ks < 4; ks++) {
            int ko = ks * 32;
            uint32_t fa[4][4], fh[2][4], fl[2][4];
            #pragma unroll
            for (int mt = 0; mt < 4; mt++) LDSM_X4(fa[mt], adA + mt * 16 * LDT * 2 + ko);
            #pragma unroll
            for (int p = 0; p < 2; p++)    LDSM_X4(fh[p], adBh + p * 16 * LDT * 2 + ko);
            #pragma unroll
            for (int p = 0; p < 2; p++)    LDSM_X4(fl[p], adBl + p * 16 * LDT * 2 + ko);
            #pragma unroll
            for (int mt = 0; mt < 4; mt++)
                #pragma unroll
                for (int nt = 0; nt < 4; nt++)
                    MMA16816H(acc[mt][nt], fa[mt],
                              fh[nt >> 1][(nt & 1) * 2], fh[nt >> 1][(nt & 1) * 2 + 1]);
            #pragma unroll
            for (int mt = 0; mt < 4; mt++)
                #pragma unroll
                for (int nt = 0; nt < 4; nt++)
                    MMA16816H(acc[mt][nt], fa[mt],
                              fl[nt >> 1][(nt & 1) * 2], fl[nt >> 1][(nt & 1) * 2 + 1]);
        }
        __syncthreads();
    }

    int er = lane >> 2, ec = (lane & 3) * 2;
    #pragma unroll
    for (int mt = 0; mt < 4; mt++) {
        #pragma unroll
        for (int nt = 0; nt < 4; nt++) {
            float* d = acc[mt][nt];
            int mr = m0 + wm + mt * 16 + er;
            int nc = n0 + wn + nt * 8 + ec;
            #pragma unroll
            for (int q = 0; q < 4; q++) {
                int m = mr + (q >> 1) * 8;
                int n = nc + (q & 1);
                size_t o = (size_t)m * ldc + n;
                __nv_bfloat16 h, l;
                bsplit(d[q], h, l);
                Coh[o] = h; Col[o] = l;
            }
        }
    }
}

// ==================== masked softmax -> fp16 alpha ====================
__global__ void softmax_kernel(const unsigned char* __restrict__ mask)
{
    int gw = (blockIdx.x * blockDim.x + threadIdx.x) >> 5;
    int lane = threadIdx.x & 31;
    int z = gw >> 9;
    int b = z / 3;
    const float* s = g_scores + (size_t)gw * Lk;
    const unsigned char* mk = mask + b * Lk;

    float v[16];
    float mx = -INFINITY;
    #pragma unroll
    for (int t = 0; t < 16; t++) {
        int m = lane + t * 32;
        float x = s[m];
        if (mk[m]) x = NEGF;
        v[t] = x;
        mx = fmaxf(mx, x);
    }
    #pragma unroll
    for (int o = 16; o > 0; o >>= 1) mx = fmaxf(mx, __shfl_xor_sync(0xffffffffu, mx, o));
    float sum = 0.f;
    #pragma unroll
    for (int t = 0; t < 16; t++) { v[t] = expf(v[t] - mx); sum += v[t]; }
    #pragma unroll
    for (int o = 16; o > 0; o >>= 1) sum += __shfl_xor_sync(0xffffffffu, sum, o);
    float inv = 1.f / sum;
    size_t base = (size_t)gw * Lk;
    #pragma unroll
    for (int t = 0; t < 16; t++)
        g_ah[base + lane + t * 32] = __float2half(v[t] * inv);
}

// ==================== BiLSTM recurrence (88/40 weight split, R12 proven) ====================
#define LSTM_SMEM (512 * 16 * 16 + 128 * 4 + 512 * 4)

__global__ void __launch_bounds__(512, 1)
lstm_kernel(const float* __restrict__ WhhF, const float* __restrict__ WhhB,
            float* __restrict__ out)
{
    extern __shared__ float sm[];
    double2* Wsm2 = (double2*)sm;          // [512][16] double2 slots, swizzled, 10 used
    float*   hs   = sm + 32768;
    float*   as   = sm + 32768 + 128;

    int dir = blockIdx.x >> 4;
    int b   = blockIdx.x & 15;
    const float* Whh = dir ? WhhB : WhhF;
    const float* g   = dir ? g_gb : g_gf;
    int j = threadIdx.x;
    int grp = j >> 7;

    unsigned long long w2[44];
    #pragma unroll
    for (int c = 0; c < 22; c++) {
        double2 t = *(const double2*)(Whh + (size_t)j * Hh + c * 4);
        w2[2*c]   = __double_as_longlong(t.x);
        w2[2*c+1] = __double_as_longlong(t.y);
    }
    #pragma unroll
    for (int c = 0; c < 10; c++) {
        double2 t = *(const double2*)(Whh + (size_t)j * Hh + 88 + c * 4);
        Wsm2[j * 16 + (c ^ (j & 7))] = t;
    }
    if (j < Hh) hs[j] = 0.f;
    float cst = 0.f;
    __syncthreads();

    int l  = dir ? (Lq - 1) : 0;
    int dl = dir ? -1 : 1;
    float gval = g[((size_t)l * Bsz + b) * G4 + j];

    #pragma unroll 1
    for (int s = 0; s < Lq; s++) {
        float gnext = 0.f;
        if (s < Lq - 1) gnext = g[((size_t)(l + dl) * Bsz + b) * G4 + j];

        const double2* h2 = (const double2*)hs;
        unsigned long long p0 = (unsigned long long)__float_as_uint(gval);
        unsigned long long p1 = 0ull, p2 = 0ull, p3 = 0ull;
        #pragma unroll
        for (int c = 0; c < 22; c++) {
            double2 hv = h2[c];
            FMA2(p0, w2[2*c],   __double_as_longlong(hv.x));
            FMA2(p1, w2[2*c+1], __double_as_longlong(hv.y));
        }
        #pragma unroll
        for (int c = 0; c < 10; c++) {
            double2 hv = h2[22 + c];
            double2 wv = Wsm2[j * 16 + (c ^ (j & 7))];
            FMA2(p2, __double_as_longlong(wv.x), __double_as_longlong(hv.x));
            FMA2(p3, __double_as_longlong(wv.y), __double_as_longlong(hv.y));
        }
        float z = (__uint_as_float((unsigned)p0) + __uint_as_float((unsigned)(p0 >> 32)))
                + (__uint_as_float((unsigned)p1) + __uint_as_float((unsigned)(p1 >> 32)))
                + (__uint_as_float((unsigned)p2) + __uint_as_float((unsigned)(p2 >> 32)))
                + (__uint_as_float((unsigned)p3) + __uint_as_float((unsigned)(p3 >> 32)));
        as[j] = (grp == 2) ? tanhf(z) : (1.f / (1.f + expf(-z)));
        __syncthreads();

        if (j < Hh) {
            float si = as[j], sf = as[Hh + j], tg = as[2*Hh + j], so = as[3*Hh + j];
            cst = sf * cst + si * tg;
            float hv = so * tanhf(cst);
            hs[j] = hv;
            out[((size_t)b * Lq + l) * 256 + dir * Hh + j] = hv;
        }
        __syncthreads();
        gval = gnext;
        l += dl;
    }
}

// ==================== launcher ====================
extern "C" void kernel_launch(void* const* d_in, const int* in_sizes, int n_in,
                              void* d_out, int out_size)
{
    const float* x1_word = (const float*)d_in[0];
    const float* x1_a0   = (const float*)d_in[1];
    const float* x1_a1   = (const float*)d_in[2];
    const float* x2_word = (const float*)d_in[3];
    const float* x2_a0   = (const float*)d_in[4];
    const float* x2_a1   = (const float*)d_in[5];
    const float* x2_a2   = (const float*)d_in[6];
    const unsigned char* x2_mask = (const unsigned char*)d_in[8];
    const float* W_attn  = (const float*)d_in[9];
    const float* v_attn  = (const float*)d_in[10];
    const float* Wih_f   = (const float*)d_in[11];
    const float* Whh_f   = (const float*)d_in[12];
    const float* b_f     = (const float*)d_in[13];
    const float* Wih_b   = (const float*)d_in[14];
    const float* Whh_b   = (const float*)d_in[15];
    const float* b_b     = (const float*)d_in[16];
    float* out = (float*)d_out;

    cudaFuncSetAttribute(lstm_kernel,
                         cudaFuncAttributeMaxDynamicSharedMemorySize, LSTM_SMEM);
    cudaFuncSetAttribute(tgemm_kernel,
                         cudaFuncAttributeMaxDynamicSharedMemorySize, TG_SMEM);
    cudaFuncSetAttribute(tgemm_av_kernel,
                         cudaFuncAttributeMaxDynamicSharedMemorySize, TG_SMEM);

    __nv_bfloat16 *p_wfh, *p_wfl, *p_wbh, *p_wbl;
    cudaGetSymbolAddress((void**)&p_wfh, g_wfh); cudaGetSymbolAddress((void**)&p_wfl, g_wfl);
    cudaGetSymbolAddress((void**)&p_wbh, g_wbh); cudaGetSymbolAddress((void**)&p_wbl, g_wbl);

    // launches 1-3: prerequisites of the projection GEMM
    vpad_kernel<<<3, 256>>>(v_attn);
    pad_w_kernel<<<(NP * KA + 255) / 256, 256>>>(W_attn);
    dim3 gb((Bsz * Lq * KA + 255) / 256, 2);
    build_att_kernel<<<gb, 256>>>(x1_word, x1_a0, x1_a1, x2_word, x2_a0, x2_a1);

    // launch 4 (profiled): merged projections M=8192 N=768 K=832, z in {x1,x2}
    dim3 gp(NP / 128, (Bsz * Lq) / 128, 2);
    tgemm_kernel<<<gp, 256, TG_SMEM>>>(0, nullptr, nullptr);

    conv_split_kernel<<<(G4 * RNN_IN + 255) / 256, 256>>>(Wih_f, p_wfh, p_wfl, G4 * RNN_IN);
    conv_split_kernel<<<(G4 * RNN_IN + 255) / 256, 256>>>(Wih_b, p_wbh, p_wbl, G4 * RNN_IN);
    fill_x1cat_base<<<(Lq * Bsz * 2 * AH + 255) / 256, 256>>>(x1_a0, x1_a1);
    vt_build_kernel<<<(3 * Bsz * AH * Lk + 255) / 256, 256>>>(x2_a0, x2_a1, x2_a2);

    // scores : 48 x [512,512,K=256], bf16 3-pass
    dim3 gs(Lk / 128, Lq / 128, 48);
    tgemm_kernel<<<gs, 256, TG_SMEM>>>(2, nullptr, nullptr);

    softmax_kernel<<<(48 * Lq) / 8, 256>>>(x2_mask);

    // alpha @ V : 48 x [512,256,K=512], fp16 2-pass dedicated kernel
    dim3 gav(AH / 128, Lq / 128, 48);
    tgemm_av_kernel<<<gav, 256, TG_SMEM>>>();

    // LSTM input gates merged: M=8192, N=512, K=1280, z in {f,b}, bf16 3-pass
    dim3 gg(G4 / 128, (Bsz * Lq) / 128, 2);
    tgemm_kernel<<<gg, 256, TG_SMEM>>>(4, b_f, b_b);

    lstm_kernel<<<32, 512, LSTM_SMEM>>>(Whh_f, Whh_b, out);
}

// round 16
// speedup vs baseline: 1.0929x; 1.0498x over previous
#include <cuda_runtime.h>
#include <cuda_bf16.h>
#include <cuda_fp16.h>
#include <cstdint>
#include <math.h>

#define Bsz 16
#define Lq 512
#define Lk 512
#define EMB 300
#define AH 256
#define ATT 250
#define ATT_IN 812
#define KA 832        // ATT_IN padded to 13*64
#define NP 768        // 3 heads * 256 (padded from 750)
#define RNN_IN 1280
#define Hh 128
#define G4 512

#define NEGF (-3.402823466e38f)
#define LDT 72        // 64 + 8 pad (bf16 elems) -> 144B row stride, conflict-free

// ==================== scratch (device globals) ====================
__device__ alignas(16) __nv_bfloat16 g_x1h[Bsz*Lq*KA], g_x1l[Bsz*Lq*KA];
__device__ alignas(16) __nv_bfloat16 g_x2h[Bsz*Lk*KA], g_x2l[Bsz*Lk*KA];
__device__ alignas(16) __nv_bfloat16 g_wh[NP*KA],      g_wl[NP*KA];
__device__ alignas(16) __nv_bfloat16 g_r1h[Bsz*Lq*NP], g_r1l[Bsz*Lq*NP];
__device__ alignas(16) __nv_bfloat16 g_r2h[Bsz*Lk*NP], g_r2l[Bsz*Lk*NP];
__device__ alignas(16) float         g_scores[48*Lq*Lk];
__device__ alignas(16) __half        g_ah[48*Lq*Lk];            // alpha, single fp16
__device__ alignas(16) __half        g_vth[3*Bsz*AH*Lk], g_vtl[3*Bsz*AH*Lk];  // V fp16 hi/lo
__device__ alignas(16) __nv_bfloat16 g_xch[Lq*Bsz*RNN_IN], g_xcl[Lq*Bsz*RNN_IN];
__device__ alignas(16) __nv_bfloat16 g_wfh[G4*RNN_IN], g_wfl[G4*RNN_IN];
__device__ alignas(16) __nv_bfloat16 g_wbh[G4*RNN_IN], g_wbl[G4*RNN_IN];
__device__ alignas(16) float g_gf[Lq*Bsz*G4];
__device__ alignas(16) float g_gb[Lq*Bsz*G4];
__device__ alignas(16) float g_vpad[NP];
__device__ int g_cnt[2][64];     // gates tile completion counters

__device__ __forceinline__ void bsplit(float v, __nv_bfloat16& h, __nv_bfloat16& l) {
    h = __float2bfloat16(v);
    l = __float2bfloat16(v - __bfloat162float(h));
}
__device__ __forceinline__ void hsplit(float v, __half& h, __half& l) {
    h = __float2half(v);
    l = __float2half(v - __half2float(h));
}

__device__ __forceinline__ uint32_t smem_u32(const void* p) {
    uint32_t a;
    asm("{ .reg .u64 t; cvta.to.shared.u64 t, %1; cvt.u32.u64 %0, t; }"
        : "=r"(a) : "l"(p));
    return a;
}

#define LDSM_X4(r, addr) \
    asm volatile("ldmatrix.sync.aligned.m8n8.x4.shared.b16 {%0,%1,%2,%3}, [%4];" \
        : "=r"((r)[0]), "=r"((r)[1]), "=r"((r)[2]), "=r"((r)[3]) : "r"(addr))

#define MMA16816(d, a, bb0, bb1) \
    asm volatile("mma.sync.aligned.m16n8k16.row.col.f32.bf16.bf16.f32 " \
        "{%0,%1,%2,%3}, {%4,%5,%6,%7}, {%8,%9}, {%0,%1,%2,%3};" \
        : "+f"((d)[0]), "+f"((d)[1]), "+f"((d)[2]), "+f"((d)[3]) \
        : "r"((a)[0]), "r"((a)[1]), "r"((a)[2]), "r"((a)[3]), "r"(bb0), "r"(bb1))

#define MMA16816H(d, a, bb0, bb1) \
    asm volatile("mma.sync.aligned.m16n8k16.row.col.f32.f16.f16.f32 " \
        "{%0,%1,%2,%3}, {%4,%5,%6,%7}, {%8,%9}, {%0,%1,%2,%3};" \
        : "+f"((d)[0]), "+f"((d)[1]), "+f"((d)[2]), "+f"((d)[3]) \
        : "r"((a)[0]), "r"((a)[1]), "r"((a)[2]), "r"((a)[3]), "r"(bb0), "r"(bb1))

#define CP16(dst, src) \
    asm volatile("cp.async.cg.shared.global [%0], [%1], 16;" :: "r"(dst), "l"(src))
#define CP_COMMIT() asm volatile("cp.async.commit_group;" ::: "memory")
#define CP_WAIT2()  asm volatile("cp.async.wait_group 2;" ::: "memory")
#define CP_WAIT1()  asm volatile("cp.async.wait_group 1;" ::: "memory")
#define CP_WAIT0()  asm volatile("cp.async.wait_group 0;" ::: "memory")

// packed f32x2 FMA (Blackwell)
#define FMA2(d, a, b) \
    asm("fma.rn.f32x2 %0, %1, %2, %3;" : "=l"(d) : "l"(a), "l"(b), "l"(d))

// ==================== builders ====================
__global__ void pad_w_kernel(const float* __restrict__ W)
{
    int idx = blockIdx.x * blockDim.x + threadIdx.x;
    if (idx >= NP * KA) return;
    int k = idx % KA, rr = idx / KA;
    int i = rr >> 8, j = rr & 255;
    float v = (j < ATT && k < ATT_IN) ? W[((size_t)(i * ATT + j)) * ATT_IN + k] : 0.f;
    bsplit(v, g_wh[idx], g_wl[idx]);
}

__global__ void vpad_kernel(const float* __restrict__ v)
{
    int n = blockIdx.x * blockDim.x + threadIdx.x;
    if (n >= NP) return;
    int i = n >> 8, j = n & 255;
    g_vpad[n] = (j < ATT) ? v[i * ATT + j] : 0.f;
}

__global__ void conv_split_kernel(const float* __restrict__ src,
                                  __nv_bfloat16* __restrict__ dh,
                                  __nv_bfloat16* __restrict__ dl, int n)
{
    int idx = blockIdx.x * blockDim.x + threadIdx.x;
    if (idx >= n) return;
    bsplit(src[idx], dh[idx], dl[idx]);
}

// merged x1/x2 builder: blockIdx.y selects side
__global__ void build_att_kernel(const float* __restrict__ w1,
                                 const float* __restrict__ a10,
                                 const float* __restrict__ a11,
                                 const float* __restrict__ w2,
                                 const float* __restrict__ a20,
                                 const float* __restrict__ a21)
{
    int idx = blockIdx.x * blockDim.x + threadIdx.x;
    if (idx >= Bsz * Lq * KA) return;
    int z = blockIdx.y;
    const float* w  = z ? w2  : w1;
    const float* a0 = z ? a20 : a10;
    const float* a1 = z ? a21 : a11;
    __nv_bfloat16* dh = z ? g_x2h : g_x1h;
    __nv_bfloat16* dl = z ? g_x2l : g_x1l;
    int f = idx % KA;
    int bl = idx / KA;
    float v = 0.f;
    if (f < EMB)            v = w[(size_t)bl * EMB + f];
    else if (f < EMB + AH)  v = a0[(size_t)bl * AH + (f - EMB)];
    else if (f < ATT_IN)    v = a1[(size_t)bl * AH + (f - EMB - AH)];
    bsplit(v, dh[idx], dl[idx]);
}

__global__ void fill_x1cat_base(const float* __restrict__ a0,
                                const float* __restrict__ a1)
{
    int idx = blockIdx.x * blockDim.x + threadIdx.x;
    if (idx >= Lq * Bsz * 2 * AH) return;
    int f = idx % (2 * AH);
    int lb = idx / (2 * AH);
    int l = lb / Bsz, b = lb % Bsz;
    float v = (f < AH) ? a0[((size_t)b * Lq + l) * AH + f]
                       : a1[((size_t)b * Lq + l) * AH + (f - AH)];
    size_t off = (size_t)lb * RNN_IN + f;
    bsplit(v, g_xch[off], g_xcl[off]);
}

// V transpose: fp16 hi/lo split
__global__ void vt_build_kernel(const float* __restrict__ a0,
                                const float* __restrict__ a1,
                                const float* __restrict__ a2)
{
    int idx = blockIdx.x * blockDim.x + threadIdx.x;
    if (idx >= 3 * Bsz * AH * Lk) return;
    int l = idx & 511, d = (idx >> 9) & 255, b = (idx >> 17) & 15, i = idx >> 21;
    const float* src = (i == 0) ? a0 : (i == 1 ? a1 : a2);
    hsplit(src[((size_t)b * Lk + l) * AH + d], g_vth[idx], g_vtl[idx]);
}

// ==================== bf16 3-pass GEMM: exact R12/R15 body (modes 0/2) ====================
#define TGB (4 * 128 * LDT * 2)     // 73728 B per stage
#define TG_SMEM (3 * TGB)           // 221184 B

__global__ void __launch_bounds__(256)
tgemm_kernel(int mode, const float* __restrict__ v0, const float* __restrict__ v1)
{
    extern __shared__ char smem[];

    const __nv_bfloat16 *Ah, *Al, *Bh, *Bl;
    float* Cf = nullptr;
    __nv_bfloat16 *Coh = nullptr, *Col = nullptr;
    const float* vec = v0;
    int lda, ldb, ldc, K, epi;

    if (mode == 0) {
        int z = blockIdx.z;
        Ah = z ? g_x2h : g_x1h; Al = z ? g_x2l : g_x1l;
        Bh = g_wh; Bl = g_wl;
        Coh = z ? g_r2h : g_r1h; Col = z ? g_r2l : g_r1l;
        lda = KA; ldb = KA; ldc = NP; K = KA;
        epi = z ? 2 : 1; vec = g_vpad;
    } else if (mode == 2) {
        int z = blockIdx.z, b = z / 3, i = z - b * 3;
        size_t off = (size_t)b * Lq * NP + (size_t)i * 256;
        Ah = g_r1h + off; Al = g_r1l + off;
        Bh = g_r2h + off; Bl = g_r2l + off;
        Cf = g_scores + (size_t)z * Lq * Lk;
        lda = NP; ldb = NP; ldc = Lk; K = 256; epi = 0;
    } else {
        int z = blockIdx.z;
        Ah = g_xch; Al = g_xcl;
        Bh = z ? g_wbh : g_wfh; Bl = z ? g_wbl : g_wfl;
        Cf = z ? g_gb : g_gf;
        vec = z ? v1 : v0;
        lda = RNN_IN; ldb = RNN_IN; ldc = G4; K = RNN_IN; epi = 4;
    }

    int m0 = blockIdx.y * 128, n0 = blockIdx.x * 128;
    int tid = threadIdx.x, lane = tid & 31, wid = tid >> 5;
    int wm = (wid >> 2) * 64, wn = (wid & 3) * 32;

    float acc[4][4][4];
    #pragma unroll
    for (int a = 0; a < 4; a++)
        #pragma unroll
        for (int b = 0; b < 4; b++)
            #pragma unroll
            for (int c = 0; c < 4; c++) acc[a][b][c] = 0.f;

    int arow = lane & 15, akk = (lane >> 4) * 8;
    int brow = (lane & 7) + ((lane >> 4) * 8), bkk = ((lane >> 3) & 1) * 8;

    uint32_t sbase = smem_u32(smem);
    const uint32_t tB = 128 * LDT * 2;

    int ldrow = tid >> 3, ldc8 = (tid & 7) * 8;
    uint32_t so0 = (uint32_t)((ldrow * LDT + ldc8) * 2);

    int nch = K >> 6;

    auto issue = [&](int kc, int buf) {
        int kb = kc * 64;
        uint32_t bb = sbase + buf * TGB;
        #pragma unroll
        for (int i = 0; i < 4; i++) {
            int row = ldrow + i * 32;
            uint32_t so = bb + so0 + (uint32_t)(i * 32 * LDT * 2);
            CP16(so,          Ah + (size_t)(m0 + row) * lda + kb + ldc8);
            CP16(so + tB,     Al + (size_t)(m0 + row) * lda + kb + ldc8);
            CP16(so + 2 * tB, Bh + (size_t)(n0 + row) * ldb + kb + ldc8);
            CP16(so + 3 * tB, Bl + (size_t)(n0 + row) * ldb + kb + ldc8);
        }
        CP_COMMIT();
    };

    issue(0, 0);
    if (nch > 1) issue(1, 1);

    for (int kc = 0; kc < nch; kc++) {
        int buf = kc % 3;
        if (kc + 2 < nch)      { issue(kc + 2, (kc + 2) % 3); CP_WAIT2(); }
        else if (kc + 1 < nch) { CP_WAIT1(); }
        else                   { CP_WAIT0(); }
        __syncthreads();

        uint32_t bb = sbase + buf * TGB;
        uint32_t adAh = bb + ((wm + arow) * LDT + akk) * 2;
        uint32_t adAl = adAh + tB;
        uint32_t adBh = bb + 2 * tB + ((wn + brow) * LDT + bkk) * 2;
        uint32_t adBl = adBh + tB;

        uint32_t fah[2][4][4], fbh[2][2][4];
        #pragma unroll
        for (int mt = 0; mt < 4; mt++) LDSM_X4(fah[0][mt], adAh + mt * 16 * LDT * 2);
        #pragma unroll
        for (int p = 0; p < 2; p++)    LDSM_X4(fbh[0][p], adBh + p * 16 * LDT * 2);

        #pragma unroll
        for (int ks = 0; ks < 4; ks++) {
            const int cur = ks & 1, nxt = cur ^ 1;
            int ko = ks * 32;

            uint32_t fbl[2][4], fal[4][4];
            #pragma unroll
            for (int p = 0; p < 2; p++)    LDSM_X4(fbl[p], adBl + p * 16 * LDT * 2 + ko);
            #pragma unroll
            for (int mt = 0; mt < 4; mt++) LDSM_X4(fal[mt], adAl + mt * 16 * LDT * 2 + ko);
            if (ks < 3) {
                #pragma unroll
                for (int mt = 0; mt < 4; mt++) LDSM_X4(fah[nxt][mt], adAh + mt * 16 * LDT * 2 + ko + 32);
                #pragma unroll
                for (int p = 0; p < 2; p++)    LDSM_X4(fbh[nxt][p], adBh + p * 16 * LDT * 2 + ko + 32);
            }

            #pragma unroll
            for (int mt = 0; mt < 4; mt++)
                #pragma unroll
                for (int nt = 0; nt < 4; nt++)
                    MMA16816(acc[mt][nt], fah[cur][mt],
                             fbh[cur][nt >> 1][(nt & 1) * 2], fbh[cur][nt >> 1][(nt & 1) * 2 + 1]);
            #pragma unroll
            for (int mt = 0; mt < 4; mt++)
                #pragma unroll
                for (int nt = 0; nt < 4; nt++)
                    MMA16816(acc[mt][nt], fah[cur][mt],
                             fbl[nt >> 1][(nt & 1) * 2], fbl[nt >> 1][(nt & 1) * 2 + 1]);
            #pragma unroll
            for (int mt = 0; mt < 4; mt++)
                #pragma unroll
                for (int nt = 0; nt < 4; nt++)
                    MMA16816(acc[mt][nt], fal[mt],
                             fbh[cur][nt >> 1][(nt & 1) * 2], fbh[cur][nt >> 1][(nt & 1) * 2 + 1]);
        }
        __syncthreads();
    }

    int er = lane >> 2, ec = (lane & 3) * 2;
    #pragma unroll
    for (int mt = 0; mt < 4; mt++) {
        #pragma unroll
        for (int nt = 0; nt < 4; nt++) {
            float* d = acc[mt][nt];
            int mr = m0 + wm + mt * 16 + er;
            int nc = n0 + wn + nt * 8 + ec;
            #pragma unroll
            for (int q = 0; q < 4; q++) {
                int m = mr + (q >> 1) * 8;
                int n = nc + (q & 1);
                float v = d[q];
                if (epi == 0) {
                    Cf[(size_t)m * ldc + n] = v;
                } else if (epi == 4) {
                    Cf[(size_t)m * ldc + n] = v + vec[n];
                } else {
                    if (epi == 1) v = fmaxf(v, 0.f);
                    else if (epi == 2) v = fmaxf(v, 0.f) * vec[n];
                    size_t o = (size_t)m * ldc + n;
                    __nv_bfloat16 h, l;
                    bsplit(v, h, l);
                    Coh[o] = h; Col[o] = l;
                }
            }
        }
    }
}

// ==================== fp16 2-pass alpha@V GEMM ====================
__global__ void __launch_bounds__(256)
tgemm_av_kernel()
{
    extern __shared__ char smem[];

    int z = blockIdx.z, b = z / 3, i = z - b * 3;
    const __half* Ax = g_ah + (size_t)z * Lq * Lk;
    size_t boff = (size_t)(i * Bsz + b) * AH * Lk;
    const __half* Bh = g_vth + boff;
    const __half* Bl = g_vtl + boff;
    size_t coff = (size_t)b * RNN_IN + 2 * AH + (size_t)i * AH;
    __nv_bfloat16* Coh = g_xch + coff;
    __nv_bfloat16* Col = g_xcl + coff;
    const int lda = Lk, ldb = Lk, ldc = Bsz * RNN_IN, K = Lk;

    int m0 = blockIdx.y * 128, n0 = blockIdx.x * 128;
    int tid = threadIdx.x, lane = tid & 31, wid = tid >> 5;
    int wm = (wid >> 2) * 64, wn = (wid & 3) * 32;

    float acc[4][4][4];
    #pragma unroll
    for (int a = 0; a < 4; a++)
        #pragma unroll
        for (int bq = 0; bq < 4; bq++)
            #pragma unroll
            for (int c = 0; c < 4; c++) acc[a][bq][c] = 0.f;

    int arow = lane & 15, akk = (lane >> 4) * 8;
    int brow = (lane & 7) + ((lane >> 4) * 8), bkk = ((lane >> 3) & 1) * 8;

    uint32_t sbase = smem_u32(smem);
    const uint32_t tB = 128 * LDT * 2;

    int ldrow = tid >> 3, ldc8 = (tid & 7) * 8;
    uint32_t so0 = (uint32_t)((ldrow * LDT + ldc8) * 2);

    int nch = K >> 6;

    auto issue = [&](int kc, int buf) {
        int kb = kc * 64;
        uint32_t bb = sbase + buf * TGB;
        #pragma unroll
        for (int u = 0; u < 4; u++) {
            int row = ldrow + u * 32;
            uint32_t so = bb + so0 + (uint32_t)(u * 32 * LDT * 2);
            CP16(so,          Ax + (size_t)(m0 + row) * lda + kb + ldc8);
            CP16(so + tB,     Bh + (size_t)(n0 + row) * ldb + kb + ldc8);
            CP16(so + 2 * tB, Bl + (size_t)(n0 + row) * ldb + kb + ldc8);
        }
        CP_COMMIT();
    };

    issue(0, 0);
    if (nch > 1) issue(1, 1);

    for (int kc = 0; kc < nch; kc++) {
        int buf = kc % 3;
        if (kc + 2 < nch)      { issue(kc + 2, (kc + 2) % 3); CP_WAIT2(); }
        else if (kc + 1 < nch) { CP_WAIT1(); }
        else                   { CP_WAIT0(); }
        __syncthreads();

        uint32_t bb = sbase + buf * TGB;
        uint32_t adA  = bb + ((wm + arow) * LDT + akk) * 2;
        uint32_t adBh = bb + tB + ((wn + brow) * LDT + bkk) * 2;
        uint32_t adBl = adBh + tB;

        #pragma unroll
        for (int ks = 0; ks < 4; ks++) {
            int ko = ks * 32;
            uint32_t fa[4][4], fh[2][4], fl[2][4];
            #pragma unroll
            for (int mt = 0; mt < 4; mt++) LDSM_X4(fa[mt], adA + mt * 16 * LDT * 2 + ko);
            #pragma unroll
            for (int p = 0; p < 2; p++)    LDSM_X4(fh[p], adBh + p * 16 * LDT * 2 + ko);
            #pragma unroll
            for (int p = 0; p < 2; p++)    LDSM_X4(fl[p], adBl + p * 16 * LDT * 2 + ko);
            #pragma unroll
            for (int mt = 0; mt < 4; mt++)
                #pragma unroll
                for (int nt = 0; nt < 4; nt++)
                    MMA16816H(acc[mt][nt], fa[mt],
                              fh[nt >> 1][(nt & 1) * 2], fh[nt >> 1][(nt & 1) * 2 + 1]);
            #pragma unroll
            for (int mt = 0; mt < 4; mt++)
                #pragma unroll
                for (int nt = 0; nt < 4; nt++)
                    MMA16816H(acc[mt][nt], fa[mt],
                              fl[nt >> 1][(nt & 1) * 2], fl[nt >> 1][(nt & 1) * 2 + 1]);
        }
        __syncthreads();
    }

    int er = lane >> 2, ec = (lane & 3) * 2;
    #pragma unroll
    for (int mt = 0; mt < 4; mt++) {
        #pragma unroll
        for (int nt = 0; nt < 4; nt++) {
            float* d = acc[mt][nt];
            int mr = m0 + wm + mt * 16 + er;
            int nc = n0 + wn + nt * 8 + ec;
            #pragma unroll
            for (int q = 0; q < 4; q++) {
                int m = mr + (q >> 1) * 8;
                int n = nc + (q & 1);
                size_t o = (size_t)m * ldc + n;
                __nv_bfloat16 h, l;
                bsplit(d[q], h, l);
                Coh[o] = h; Col[o] = l;
            }
        }
    }
}

// ==================== masked softmax -> fp16 alpha ====================
__global__ void softmax_kernel(const unsigned char* __restrict__ mask)
{
    int gw = (blockIdx.x * blockDim.x + threadIdx.x) >> 5;
    int lane = threadIdx.x & 31;
    int z = gw >> 9;
    int b = z / 3;
    const float* s = g_scores + (size_t)gw * Lk;
    const unsigned char* mk = mask + b * Lk;

    float v[16];
    float mx = -INFINITY;
    #pragma unroll
    for (int t = 0; t < 16; t++) {
        int m = lane + t * 32;
        float x = s[m];
        if (mk[m]) x = NEGF;
        v[t] = x;
        mx = fmaxf(mx, x);
    }
    #pragma unroll
    for (int o = 16; o > 0; o >>= 1) mx = fmaxf(mx, __shfl_xor_sync(0xffffffffu, mx, o));
    float sum = 0.f;
    #pragma unroll
    for (int t = 0; t < 16; t++) { v[t] = expf(v[t] - mx); sum += v[t]; }
    #pragma unroll
    for (int o = 16; o > 0; o >>= 1) sum += __shfl_xor_sync(0xffffffffu, sum, o);
    float inv = 1.f / sum;
    size_t base = (size_t)gw * Lk;
    #pragma unroll
    for (int t = 0; t < 16; t++)
        g_ah[base + lane + t * 32] = __float2half(v[t] * inv);
}

// ==================== fused gates GEMM + BiLSTM (producer-consumer) ====================
// grid = 544 blocks x 256 threads. bid<32: LSTM consumers. bid>=32: gates producers.
// Producers: per (zz,mtile,nx) 128x128 tile of g; flag cnt[zz][mtile] after store.
// Backward (zz=1) tiles produced high-l-first so the reverse LSTM streams too.
__global__ void __launch_bounds__(256)
gates_lstm_kernel(const float* __restrict__ bf, const float* __restrict__ bb_,
                  const float* __restrict__ WhhF, const float* __restrict__ WhhB,
                  float* __restrict__ out)
{
    extern __shared__ char smem[];
    int bid = blockIdx.x;

    if (bid >= 32) {
        // ---------------- gates GEMM producer (mode-4 body) ----------------
        int bq = bid - 32;
        int nx = bq & 3, zz = (bq >> 2) & 1, yy = bq >> 3;
        int mtile = zz ? (63 - yy) : yy;
        const __nv_bfloat16* Ah = g_xch;
        const __nv_bfloat16* Al = g_xcl;
        const __nv_bfloat16* Bh = zz ? g_wbh : g_wfh;
        const __nv_bfloat16* Bl = zz ? g_wbl : g_wfl;
        float* Cf = zz ? g_gb : g_gf;
        const float* vec = zz ? bb_ : bf;
        const int lda = RNN_IN, ldb = RNN_IN, ldc = G4, K = RNN_IN;
        int m0 = mtile * 128, n0 = nx * 128;

        int tid = threadIdx.x, lane = tid & 31, wid = tid >> 5;
        int wm = (wid >> 2) * 64, wn = (wid & 3) * 32;

        float acc[4][4][4];
        #pragma unroll
        for (int a = 0; a < 4; a++)
            #pragma unroll
            for (int b2 = 0; b2 < 4; b2++)
                #pragma unroll
                for (int c = 0; c < 4; c++) acc[a][b2][c] = 0.f;

        int arow = lane & 15, akk = (lane >> 4) * 8;
        int brow = (lane & 7) + ((lane >> 4) * 8), bkk = ((lane >> 3) & 1) * 8;

        uint32_t sbase = smem_u32(smem);
        const uint32_t tB = 128 * LDT * 2;

        int ldrow = tid >> 3, ldc8 = (tid & 7) * 8;
        uint32_t so0 = (uint32_t)((ldrow * LDT + ldc8) * 2);

        int nch = K >> 6;

        auto issue = [&](int kc, int buf) {
            int kb = kc * 64;
            uint32_t bbf = sbase + buf * TGB;
            #pragma unroll
            for (int i = 0; i < 4; i++) {
                int row = ldrow + i * 32;
                uint32_t so = bbf + so0 + (uint32_t)(i * 32 * LDT * 2);
                CP16(so,          Ah + (size_t)(m0 + row) * lda + kb + ldc8);
                CP16(so + tB,     Al + (size_t)(m0 + row) * lda + kb + ldc8);
                CP16(so + 2 * tB, Bh + (size_t)(n0 + row) * ldb + kb + ldc8);
                CP16(so + 3 * tB, Bl + (size_t)(n0 + row) * ldb + kb + ldc8);
            }
            CP_COMMIT();
        };

        issue(0, 0);
        if (nch > 1) issue(1, 1);

        for (int kc = 0; kc < nch; kc++) {
            int buf = kc % 3;
            if (kc + 2 < nch)      { issue(kc + 2, (kc + 2) % 3); CP_WAIT2(); }
            else if (kc + 1 < nch) { CP_WAIT1(); }
            else                   { CP_WAIT0(); }
            __syncthreads();

            uint32_t bbf = sbase + buf * TGB;
            uint32_t adAh = bbf + ((wm + arow) * LDT + akk) * 2;
            uint32_t adAl = adAh + tB;
            uint32_t adBh = bbf + 2 * tB + ((wn + brow) * LDT + bkk) * 2;
            uint32_t adBl = adBh + tB;

            uint32_t fah[2][4][4], fbh[2][2][4];
            #pragma unroll
            for (int mt = 0; mt < 4; mt++) LDSM_X4(fah[0][mt], adAh + mt * 16 * LDT * 2);
            #pragma unroll
            for (int p = 0; p < 2; p++)    LDSM_X4(fbh[0][p], adBh + p * 16 * LDT * 2);

            #pragma unroll
            for (int ks = 0; ks < 4; ks++) {
                const int cur = ks & 1, nxt2 = cur ^ 1;
                int ko = ks * 32;

                uint32_t fbl[2][4], fal[4][4];
                #pragma unroll
                for (int p = 0; p < 2; p++)    LDSM_X4(fbl[p], adBl + p * 16 * LDT * 2 + ko);
                #pragma unroll
                for (int mt = 0; mt < 4; mt++) LDSM_X4(fal[mt], adAl + mt * 16 * LDT * 2 + ko);
                if (ks < 3) {
                    #pragma unroll
                    for (int mt = 0; mt < 4; mt++) LDSM_X4(fah[nxt2][mt], adAh + mt * 16 * LDT * 2 + ko + 32);
                    #pragma unroll
                    for (int p = 0; p < 2; p++)    LDSM_X4(fbh[nxt2][p], adBh + p * 16 * LDT * 2 + ko + 32);
                }

                #pragma unroll
                for (int mt = 0; mt < 4; mt++)
                    #pragma unroll
                    for (int nt = 0; nt < 4; nt++)
                        MMA16816(acc[mt][nt], fah[cur][mt],
                                 fbh[cur][nt >> 1][(nt & 1) * 2], fbh[cur][nt >> 1][(nt & 1) * 2 + 1]);
                #pragma unroll
                for (int mt = 0; mt < 4; mt++)
                    #pragma unroll
                    for (int nt = 0; nt < 4; nt++)
                        MMA16816(acc[mt][nt], fah[cur][mt],
                                 fbl[nt >> 1][(nt & 1) * 2], fbl[nt >> 1][(nt & 1) * 2 + 1]);
                #pragma unroll
                for (int mt = 0; mt < 4; mt++)
                    #pragma unroll
                    for (int nt = 0; nt < 4; nt++)
                        MMA16816(acc[mt][nt], fal[mt],
                                 fbh[cur][nt >> 1][(nt & 1) * 2], fbh[cur][nt >> 1][(nt & 1) * 2 + 1]);
            }
            __syncthreads();
        }

        int er = lane >> 2, ec = (lane & 3) * 2;
        #pragma unroll
        for (int mt = 0; mt < 4; mt++) {
            #pragma unroll
            for (int nt = 0; nt < 4; nt++) {
                float* d = acc[mt][nt];
                int mr = m0 + wm + mt * 16 + er;
                int nc = n0 + wn + nt * 8 + ec;
                #pragma unroll
                for (int q = 0; q < 4; q++) {
                    int m = mr + (q >> 1) * 8;
                    int n = nc + (q & 1);
                    Cf[(size_t)m * ldc + n] = d[q] + vec[n];
                }
            }
        }
        __syncthreads();
        if (tid == 0) {
            __threadfence();
            atomicAdd(&g_cnt[zz][mtile], 1);
        }
    } else {
        // ---------------- LSTM consumer: 256 threads, 2 gate rows/thread ----------------
        float* sm = (float*)smem;
        double2* Wsm2 = (double2*)sm;            // [512][16] double2 slots, 12 used
        float*   hs   = sm + 32768;              // 131072 B offset
        float*   as   = sm + 32768 + 128;

        int dir = bid >> 4;
        int b   = bid & 15;
        const float* Whh = dir ? WhhB : WhhF;
        const float* g   = dir ? g_gb : g_gf;
        int t = threadIdx.x;
        int j0 = t, j1 = t + 256;

        // k in [0,80): registers (40 f32x2 per row); k in [80,128): smem (12 double2 per row)
        unsigned long long w0[40], w1[40];
        #pragma unroll
        for (int c = 0; c < 20; c++) {
            double2 t0 = *(const double2*)(Whh + (size_t)j0 * Hh + c * 4);
            double2 t1 = *(const double2*)(Whh + (size_t)j1 * Hh + c * 4);
            w0[2*c] = __double_as_longlong(t0.x); w0[2*c+1] = __double_as_longlong(t0.y);
            w1[2*c] = __double_as_longlong(t1.x); w1[2*c+1] = __double_as_longlong(t1.y);
        }
        #pragma unroll
        for (int c = 0; c < 12; c++) {
            Wsm2[j0 * 16 + (c ^ (j0 & 7))] = *(const double2*)(Whh + (size_t)j0 * Hh + 80 + c * 4);
            Wsm2[j1 * 16 + (c ^ (j1 & 7))] = *(const double2*)(Whh + (size_t)j1 * Hh + 80 + c * 4);
        }
        if (t < Hh) hs[t] = 0.f;
        float cst = 0.f;
        __syncthreads();

        int l  = dir ? (Lq - 1) : 0;
        int dl = dir ? -1 : 1;

        // wait for first tile
        int lastT = l >> 3;
        if (t == 0) {
            volatile int* p = &g_cnt[dir][lastT];
            while (*p < 4) __nanosleep(200);
        }
        __syncthreads();
        __threadfence();
        float gv0 = g[((size_t)l * Bsz + b) * G4 + j0];
        float gv1 = g[((size_t)l * Bsz + b) * G4 + j1];

        #pragma unroll 1
        for (int s = 0; s < Lq; s++) {
            float gn0 = 0.f, gn1 = 0.f;
            if (s < Lq - 1) {
                int ln = l + dl, tt = ln >> 3;
                if (tt != lastT) {
                    if (t == 0) {
                        volatile int* p = &g_cnt[dir][tt];
                        while (*p < 4) __nanosleep(200);
                    }
                    __syncthreads();
                    __threadfence();
                    lastT = tt;
                }
                gn0 = g[((size_t)ln * Bsz + b) * G4 + j0];
                gn1 = g[((size_t)ln * Bsz + b) * G4 + j1];
            }

            const double2* h2 = (const double2*)hs;
            unsigned long long p0 = (unsigned long long)__float_as_uint(gv0), p1 = 0ull;
            unsigned long long q0 = (unsigned long long)__float_as_uint(gv1), q1 = 0ull;
            #pragma unroll
            for (int c = 0; c < 20; c++) {
                double2 hv = h2[c];
                unsigned long long hx = __double_as_longlong(hv.x);
                unsigned long long hy = __double_as_longlong(hv.y);
                FMA2(p0, w0[2*c],   hx); FMA2(p1, w0[2*c+1], hy);
                FMA2(q0, w1[2*c],   hx); FMA2(q1, w1[2*c+1], hy);
            }
            #pragma unroll
            for (int c = 0; c < 12; c++) {
                double2 hv = h2[20 + c];
                double2 wv0 = Wsm2[j0 * 16 + (c ^ (j0 & 7))];
                double2 wv1 = Wsm2[j1 * 16 + (c ^ (j1 & 7))];
                unsigned long long hx = __double_as_longlong(hv.x);
                unsigned long long hy = __double_as_longlong(hv.y);
                FMA2(p0, __double_as_longlong(wv0.x), hx);
                FMA2(p1, __double_as_longlong(wv0.y), hy);
                FMA2(q0, __double_as_longlong(wv1.x), hx);
                FMA2(q1, __double_as_longlong(wv1.y), hy);
            }
            float z0 = (__uint_as_float((unsigned)p0) + __uint_as_float((unsigned)(p0 >> 32)))
                     + (__uint_as_float((unsigned)p1) + __uint_as_float((unsigned)(p1 >> 32)));
            float z1 = (__uint_as_float((unsigned)q0) + __uint_as_float((unsigned)(q0 >> 32)))
                     + (__uint_as_float((unsigned)q1) + __uint_as_float((unsigned)(q1 >> 32)));
            as[j0] = 1.f / (1.f + expf(-z0));                            // i / f gates
            as[j1] = (t < 128) ? tanhf(z1) : (1.f / (1.f + expf(-z1)));  // g / o gates
            __syncthreads();

            if (t < Hh) {
                float si = as[t], sf = as[Hh + t], tg = as[2*Hh + t], so = as[3*Hh + t];
                cst = sf * cst + si * tg;
                float hv = so * tanhf(cst);
                hs[t] = hv;
                out[((size_t)b * Lq + l) * 256 + dir * Hh + t] = hv;
            }
            __syncthreads();
            gv0 = gn0; gv1 = gn1;
            l += dl;
        }
    }
}

// ==================== launcher ====================
extern "C" void kernel_launch(void* const* d_in, const int* in_sizes, int n_in,
                              void* d_out, int out_size)
{
    const float* x1_word = (const float*)d_in[0];
    const float* x1_a0   = (const float*)d_in[1];
    const float* x1_a1   = (const float*)d_in[2];
    const float* x2_word = (const float*)d_in[3];
    const float* x2_a0   = (const float*)d_in[4];
    const float* x2_a1   = (const float*)d_in[5];
    const float* x2_a2   = (const float*)d_in[6];
    const unsigned char* x2_mask = (const unsigned char*)d_in[8];
    const float* W_attn  = (const float*)d_in[9];
    const float* v_attn  = (const float*)d_in[10];
    const float* Wih_f   = (const float*)d_in[11];
    const float* Whh_f   = (const float*)d_in[12];
    const float* b_f     = (const float*)d_in[13];
    const float* Wih_b   = (const float*)d_in[14];
    const float* Whh_b   = (const float*)d_in[15];
    const float* b_b     = (const float*)d_in[16];
    float* out = (float*)d_out;

    cudaFuncSetAttribute(tgemm_kernel,
                         cudaFuncAttributeMaxDynamicSharedMemorySize, TG_SMEM);
    cudaFuncSetAttribute(tgemm_av_kernel,
                         cudaFuncAttributeMaxDynamicSharedMemorySize, TG_SMEM);
    cudaFuncSetAttribute(gates_lstm_kernel,
                         cudaFuncAttributeMaxDynamicSharedMemorySize, TG_SMEM);

    __nv_bfloat16 *p_wfh, *p_wfl, *p_wbh, *p_wbl;
    int* p_cnt;
    cudaGetSymbolAddress((void**)&p_wfh, g_wfh); cudaGetSymbolAddress((void**)&p_wfl, g_wfl);
    cudaGetSymbolAddress((void**)&p_wbh, g_wbh); cudaGetSymbolAddress((void**)&p_wbl, g_wbl);
    cudaGetSymbolAddress((void**)&p_cnt, g_cnt);

    // launches 1-3: prerequisites of the projection GEMM
    vpad_kernel<<<3, 256>>>(v_attn);
    pad_w_kernel<<<(NP * KA + 255) / 256, 256>>>(W_attn);
    dim3 gb((Bsz * Lq * KA + 255) / 256, 2);
    build_att_kernel<<<gb, 256>>>(x1_word, x1_a0, x1_a1, x2_word, x2_a0, x2_a1);

    // launch 4 (profiled): merged projections M=8192 N=768 K=832, z in {x1,x2}
    dim3 gp(NP / 128, (Bsz * Lq) / 128, 2);
    tgemm_kernel<<<gp, 256, TG_SMEM>>>(0, nullptr, nullptr);

    conv_split_kernel<<<(G4 * RNN_IN + 255) / 256, 256>>>(Wih_f, p_wfh, p_wfl, G4 * RNN_IN);
    conv_split_kernel<<<(G4 * RNN_IN + 255) / 256, 256>>>(Wih_b, p_wbh, p_wbl, G4 * RNN_IN);
    fill_x1cat_base<<<(Lq * Bsz * 2 * AH + 255) / 256, 256>>>(x1_a0, x1_a1);
    vt_build_kernel<<<(3 * Bsz * AH * Lk + 255) / 256, 256>>>(x2_a0, x2_a1, x2_a2);

    // scores : 48 x [512,512,K=256], bf16 3-pass
    dim3 gs(Lk / 128, Lq / 128, 48);
    tgemm_kernel<<<gs, 256, TG_SMEM>>>(2, nullptr, nullptr);

    softmax_kernel<<<(48 * Lq) / 8, 256>>>(x2_mask);

    // alpha @ V : 48 x [512,256,K=512], fp16 2-pass
    dim3 gav(AH / 128, Lq / 128, 48);
    tgemm_av_kernel<<<gav, 256, TG_SMEM>>>();

    // fused gates GEMM + BiLSTM with producer-consumer overlap
    cudaMemsetAsync(p_cnt, 0, sizeof(int) * 128);
    gates_lstm_kernel<<<544, 256, TG_SMEM>>>(b_f, b_b, Whh_f, Whh_b, out);
}